// round 1
// baseline (speedup 1.0000x reference)
#include <cuda_runtime.h>
#include <cstdint>

#define DEV_INLINE __device__ __forceinline__

constexpr int Bb  = 256;
constexpr int Nn  = 196;
constexpr int Cc  = 768;
constexpr int Hh  = 12;
constexpr int HD  = 64;
constexpr int Mtot = Bb * Nn;          // 50176

// ---------------- scratch (device globals — allocation-free rule) ----------
__device__ float g_Q[(size_t)Bb * Hh * Nn * HD];   // [b,h,n,d], pre-scaled
__device__ float g_K[(size_t)Bb * Hh * Nn * HD];
__device__ float g_V[(size_t)Bb * Hh * Nn * HD];
__device__ float g_Ob[(size_t)Mtot * Cc];          // attention out, [B*N, C]
__device__ float g_rpb[Hh * Nn * Nn];              // [h, n, m]

// ---------------- helpers ----------------
DEV_INLINE uint32_t f2tf(float x) {
    uint32_t r;
    asm("cvt.rna.tf32.f32 %0, %1;" : "=r"(r) : "f"(x));
    return r;
}

DEV_INLINE void mma8(float* c, const uint32_t* a, const uint32_t* b) {
    asm volatile(
        "mma.sync.aligned.m16n8k8.row.col.f32.tf32.tf32.f32 "
        "{%0,%1,%2,%3}, {%4,%5,%6,%7}, {%8,%9}, {%0,%1,%2,%3};\n"
        : "+f"(c[0]), "+f"(c[1]), "+f"(c[2]), "+f"(c[3])
        : "r"(a[0]), "r"(a[1]), "r"(a[2]), "r"(a[3]), "r"(b[0]), "r"(b[1]));
}

// ---------------- rpb precompute: g_rpb[h][n][m] = table[rel[n][m]][h] -----
__global__ void rpb_kernel(const float* __restrict__ table,
                           const int* __restrict__ rel) {
    int idx = blockIdx.x * 256 + threadIdx.x;
    if (idx >= Hh * Nn * Nn) return;
    int h = idx / (Nn * Nn);
    int r = idx - h * Nn * Nn;            // q*Nn + k
    g_rpb[idx] = table[(size_t)rel[r] * Hh + h];
}

// ---------------- 3xTF32 GEMM: C[m,j] = sum_k A[m,k] * W[j,k] (+epilogue) --
constexpr int BM = 128, BN = 64, BK = 16, PAD = 20;

DEV_INLINE void store_split(float* Sh, float* Sl, int row, int c4, float4 v) {
    float* p = (float*)&v;
    float h0 = __uint_as_float(f2tf(p[0]));
    float h1 = __uint_as_float(f2tf(p[1]));
    float h2 = __uint_as_float(f2tf(p[2]));
    float h3 = __uint_as_float(f2tf(p[3]));
    float l0 = __uint_as_float(f2tf(p[0] - h0));
    float l1 = __uint_as_float(f2tf(p[1] - h1));
    float l2 = __uint_as_float(f2tf(p[2] - h2));
    float l3 = __uint_as_float(f2tf(p[3] - h3));
    *(float4*)&Sh[row * PAD + c4] = make_float4(h0, h1, h2, h3);
    *(float4*)&Sl[row * PAD + c4] = make_float4(l0, l1, l2, l3);
}

// MODE 0: A = x, out -> g_Q/g_K/g_V with bias + q-scale
// MODE 1: A = g_Ob, out -> d_out with proj bias
template <int MODE>
__global__ void __launch_bounds__(256) gemm3x(
    const float* __restrict__ Ain, const float* __restrict__ W,
    const float* __restrict__ bias0, const float* __restrict__ bias2,
    float* __restrict__ out) {
    constexpr int K = 768;
    __shared__ float Ah[BM * PAD];
    __shared__ float Al[BM * PAD];
    __shared__ float Bh_[BN * PAD];
    __shared__ float Bl_[BN * PAD];

    const float* A = (MODE == 1) ? g_Ob : Ain;

    int tid = threadIdx.x;
    int m0 = blockIdx.y * BM, n0 = blockIdx.x * BN;
    int lane = tid & 31, wid = tid >> 5;
    int g = lane >> 2, t = lane & 3;
    int wr = (wid & 3) * 32, wc = (wid >> 2) * 32;

    const float* Ag = A + (size_t)m0 * K;
    const float* Wg = W + (size_t)n0 * K;
    int lrow = tid >> 2;
    int lc4 = (tid & 3) * 4;

    float acc[2][4][4];
#pragma unroll
    for (int i = 0; i < 2; i++)
#pragma unroll
        for (int j = 0; j < 4; j++)
#pragma unroll
            for (int e = 0; e < 4; e++) acc[i][j][e] = 0.f;

    float4 ra0, ra1, rbv;
    ra0 = *(const float4*)(Ag + (size_t)lrow * K + lc4);
    ra1 = *(const float4*)(Ag + (size_t)(lrow + 64) * K + lc4);
    rbv = *(const float4*)(Wg + (size_t)lrow * K + lc4);

    constexpr int KT = K / BK;   // 48
    for (int kt = 0; kt < KT; ++kt) {
        store_split(Ah, Al, lrow, lc4, ra0);
        store_split(Ah, Al, lrow + 64, lc4, ra1);
        store_split(Bh_, Bl_, lrow, lc4, rbv);
        __syncthreads();

        if (kt + 1 < KT) {
            int k0 = (kt + 1) * BK;
            ra0 = *(const float4*)(Ag + (size_t)lrow * K + k0 + lc4);
            ra1 = *(const float4*)(Ag + (size_t)(lrow + 64) * K + k0 + lc4);
            rbv = *(const float4*)(Wg + (size_t)lrow * K + k0 + lc4);
        }

#pragma unroll
        for (int ks = 0; ks < 2; ++ks) {
            int kk = ks * 8;
            uint32_t ah[2][4], al[2][4], bh[4][2], bl[4][2];
#pragma unroll
            for (int i = 0; i < 2; i++) {
                int r0 = wr + 16 * i + g;
                ah[i][0] = __float_as_uint(Ah[r0 * PAD + kk + t]);
                ah[i][1] = __float_as_uint(Ah[(r0 + 8) * PAD + kk + t]);
                ah[i][2] = __float_as_uint(Ah[r0 * PAD + kk + t + 4]);
                ah[i][3] = __float_as_uint(Ah[(r0 + 8) * PAD + kk + t + 4]);
                al[i][0] = __float_as_uint(Al[r0 * PAD + kk + t]);
                al[i][1] = __float_as_uint(Al[(r0 + 8) * PAD + kk + t]);
                al[i][2] = __float_as_uint(Al[r0 * PAD + kk + t + 4]);
                al[i][3] = __float_as_uint(Al[(r0 + 8) * PAD + kk + t + 4]);
            }
#pragma unroll
            for (int j = 0; j < 4; j++) {
                int n = wc + 8 * j + g;
                bh[j][0] = __float_as_uint(Bh_[n * PAD + kk + t]);
                bh[j][1] = __float_as_uint(Bh_[n * PAD + kk + t + 4]);
                bl[j][0] = __float_as_uint(Bl_[n * PAD + kk + t]);
                bl[j][1] = __float_as_uint(Bl_[n * PAD + kk + t + 4]);
            }
#pragma unroll
            for (int i = 0; i < 2; i++)
#pragma unroll
                for (int j = 0; j < 4; j++) {
                    mma8(acc[i][j], ah[i], bh[j]);
                    mma8(acc[i][j], ah[i], bl[j]);
                    mma8(acc[i][j], al[i], bh[j]);
                }
        }
        __syncthreads();
    }

    if (MODE == 0) {
        int which = n0 / Cc;                 // 0=q 1=k 2=v
        int hcol = (n0 % Cc) / HD;           // head (tile spans exactly one head)
        float* dst = (which == 0) ? g_Q : ((which == 1) ? g_K : g_V);
#pragma unroll
        for (int i = 0; i < 2; i++)
#pragma unroll
            for (int j = 0; j < 4; j++)
#pragma unroll
                for (int e2 = 0; e2 < 2; e2++) {
                    int m = m0 + wr + 16 * i + g + e2 * 8;
                    int d = wc + 8 * j + 2 * t;
                    int bb = m / Nn, nn = m - bb * Nn;
                    float v0 = acc[i][j][e2 * 2];
                    float v1 = acc[i][j][e2 * 2 + 1];
                    int r = hcol * HD + d;
                    if (which == 0) {
                        v0 = (v0 + bias0[r]) * 0.125f;
                        v1 = (v1 + bias0[r + 1]) * 0.125f;
                    } else if (which == 2) {
                        v0 += bias2[r];
                        v1 += bias2[r + 1];
                    }
                    size_t off = (((size_t)bb * Hh + hcol) * Nn + nn) * HD + d;
                    *(float2*)&dst[off] = make_float2(v0, v1);
                }
    } else {
#pragma unroll
        for (int i = 0; i < 2; i++)
#pragma unroll
            for (int j = 0; j < 4; j++)
#pragma unroll
                for (int e2 = 0; e2 < 2; e2++) {
                    int m = m0 + wr + 16 * i + g + e2 * 8;
                    int col = n0 + wc + 8 * j + 2 * t;
                    float v0 = acc[i][j][e2 * 2] + bias0[col];
                    float v1 = acc[i][j][e2 * 2 + 1] + bias0[col + 1];
                    *(float2*)&out[(size_t)m * Cc + col] = make_float2(v0, v1);
                }
    }
}

// ---------------- fused window attention --------------------
constexpr int QP = 68;    // Qs/KVs row stride (floats)
constexpr int SP = 260;   // Ss row stride (floats)
constexpr int SMEM_ATTN = (64 * QP * 2 + 64 * SP) * 4;  // 101376 B

DEV_INLINE void load_kv_chunk(float* KVs, const float* src, size_t base,
                              int kc, int tid) {
#pragma unroll
    for (int it = 0; it < 4; ++it) {
        int idx = tid + it * 256;
        int row = idx >> 4, c4 = (idx & 15) * 4;
        int kn = kc * 64 + row;
        float4 v;
        if (kn < Nn)
            v = *(const float4*)(src + base + (size_t)kn * HD + c4);
        else
            v = make_float4(0.f, 0.f, 0.f, 0.f);
        float* p = (float*)&v;
#pragma unroll
        for (int q = 0; q < 4; q++) p[q] = __uint_as_float(f2tf(p[q]));
        *(float4*)&KVs[row * QP + c4] = v;
    }
}

__global__ void __launch_bounds__(256) attn_kernel() {
    extern __shared__ float sm[];
    float* Qs = sm;                    // 64 x QP
    float* KVs = sm + 64 * QP;         // 64 x QP
    float* Ss = KVs + 64 * QP;         // 64 x SP

    int tid = threadIdx.x, wid = tid >> 5, lane = tid & 31;
    int g = lane >> 2, t = lane & 3;
    int mtile = blockIdx.x, bh = blockIdx.y;
    int b = bh / Hh, h = bh - b * Hh;
    int m0 = mtile * 64;
    size_t base = (size_t)bh * Nn * HD;
    int wr = (wid & 3) * 16, wc = (wid >> 2) * 32;

    // load Q tile (tf32-rounded; Q already carries bias + 0.125 scale)
#pragma unroll
    for (int it = 0; it < 4; ++it) {
        int idx = tid + it * 256;
        int row = idx >> 4, c4 = (idx & 15) * 4;
        int n = m0 + row;
        float4 v;
        if (n < Nn)
            v = *(const float4*)(g_Q + base + (size_t)n * HD + c4);
        else
            v = make_float4(0.f, 0.f, 0.f, 0.f);
        float* p = (float*)&v;
#pragma unroll
        for (int q = 0; q < 4; q++) p[q] = __uint_as_float(f2tf(p[q]));
        *(float4*)&Qs[row * QP + c4] = v;
    }

    // ---- phase 1: S = Q K^T + rpb -> Ss
    for (int kc = 0; kc < 4; ++kc) {
        __syncthreads();
        load_kv_chunk(KVs, g_K, base, kc, tid);
        __syncthreads();

        float acc[4][4];
#pragma unroll
        for (int j = 0; j < 4; j++)
#pragma unroll
            for (int e = 0; e < 4; e++) acc[j][e] = 0.f;

#pragma unroll
        for (int ks = 0; ks < 8; ++ks) {
            int kk = ks * 8;
            uint32_t a[4], bf[4][2];
            int r0 = wr + g;
            a[0] = __float_as_uint(Qs[r0 * QP + kk + t]);
            a[1] = __float_as_uint(Qs[(r0 + 8) * QP + kk + t]);
            a[2] = __float_as_uint(Qs[r0 * QP + kk + t + 4]);
            a[3] = __float_as_uint(Qs[(r0 + 8) * QP + kk + t + 4]);
#pragma unroll
            for (int j = 0; j < 4; j++) {
                int n = wc + 8 * j + g;     // key index in chunk
                bf[j][0] = __float_as_uint(KVs[n * QP + kk + t]);
                bf[j][1] = __float_as_uint(KVs[n * QP + kk + t + 4]);
            }
#pragma unroll
            for (int j = 0; j < 4; j++) mma8(acc[j], a, bf[j]);
        }

#pragma unroll
        for (int j = 0; j < 4; j++)
#pragma unroll
            for (int e2 = 0; e2 < 2; e2++) {
                int rl = wr + g + e2 * 8;
                int cl = wc + 8 * j + 2 * t;
                int qn = m0 + rl, kn = kc * 64 + cl;
                float r0v = 0.f, r1v = 0.f;
                if (qn < Nn) {
                    if (kn < Nn) r0v = g_rpb[((size_t)h * Nn + qn) * Nn + kn];
                    if (kn + 1 < Nn) r1v = g_rpb[((size_t)h * Nn + qn) * Nn + kn + 1];
                }
                Ss[rl * SP + kc * 64 + cl] = acc[j][e2 * 2] + r0v;
                Ss[rl * SP + kc * 64 + cl + 1] = acc[j][e2 * 2 + 1] + r1v;
            }
    }
    __syncthreads();

    // ---- softmax (warp w owns rows 8w..8w+7)
    for (int r8 = 0; r8 < 8; ++r8) {
        int r = wid * 8 + r8;
        float* row = Ss + r * SP;
        float mx = -1e30f;
#pragma unroll
        for (int c0 = 0; c0 < 7; c0++) {
            int c = lane + c0 * 32;
            if (c < Nn) mx = fmaxf(mx, row[c]);
        }
#pragma unroll
        for (int o = 16; o > 0; o >>= 1)
            mx = fmaxf(mx, __shfl_xor_sync(0xffffffffu, mx, o));
        float ev[7];
        float sum = 0.f;
#pragma unroll
        for (int c0 = 0; c0 < 7; c0++) {
            int c = lane + c0 * 32;
            float e = (c < Nn) ? __expf(row[c] - mx) : 0.f;
            ev[c0] = e;
            sum += e;
        }
#pragma unroll
        for (int o = 16; o > 0; o >>= 1)
            sum += __shfl_xor_sync(0xffffffffu, sum, o);
        float inv = 1.0f / sum;
#pragma unroll
        for (int c0 = 0; c0 < 7; c0++) {
            int c = lane + c0 * 32;
            if (c < Nn) row[c] = __uint_as_float(f2tf(ev[c0] * inv));
        }
#pragma unroll
        for (int c0 = 0; c0 < 2; c0++) {
            int c = Nn + lane + c0 * 32;
            if (c < 256) row[c] = 0.f;
        }
    }

    // ---- phase 2: O = P V
    float oac[4][4];
#pragma unroll
    for (int j = 0; j < 4; j++)
#pragma unroll
        for (int e = 0; e < 4; e++) oac[j][e] = 0.f;

    for (int kc = 0; kc < 4; ++kc) {
        __syncthreads();
        load_kv_chunk(KVs, g_V, base, kc, tid);
        __syncthreads();

#pragma unroll
        for (int ks = 0; ks < 8; ++ks) {
            int kk = kc * 64 + ks * 8;   // column in Ss (key index)
            int kl = ks * 8;             // row in KVs
            uint32_t a[4], bf[4][2];
            int r0 = wr + g;
            a[0] = __float_as_uint(Ss[r0 * SP + kk + t]);
            a[1] = __float_as_uint(Ss[(r0 + 8) * SP + kk + t]);
            a[2] = __float_as_uint(Ss[r0 * SP + kk + t + 4]);
            a[3] = __float_as_uint(Ss[(r0 + 8) * SP + kk + t + 4]);
#pragma unroll
            for (int j = 0; j < 4; j++) {
                int n = wc + 8 * j + g;  // d index
                bf[j][0] = __float_as_uint(KVs[(kl + t) * QP + n]);
                bf[j][1] = __float_as_uint(KVs[(kl + t + 4) * QP + n]);
            }
#pragma unroll
            for (int j = 0; j < 4; j++) mma8(oac[j], a, bf[j]);
        }
    }

#pragma unroll
    for (int j = 0; j < 4; j++)
#pragma unroll
        for (int e2 = 0; e2 < 2; e2++) {
            int rl = wr + g + e2 * 8;
            int n = m0 + rl;
            if (n < Nn) {
                int d = wc + 8 * j + 2 * t;
                size_t off = ((size_t)(b * Nn + n)) * Cc + h * HD + d;
                *(float2*)&g_Ob[off] =
                    make_float2(oac[j][e2 * 2], oac[j][e2 * 2 + 1]);
            }
        }
}

// ---------------- launch ----------------
extern "C" void kernel_launch(void* const* d_in, const int* in_sizes, int n_in,
                              void* d_out, int out_size) {
    const float* x = (const float*)d_in[0];
    const float* qkv_w = (const float*)d_in[1];
    const float* q_bias = (const float*)d_in[2];
    const float* v_bias = (const float*)d_in[3];
    const float* rpb_table = (const float*)d_in[4];
    const float* proj_w = (const float*)d_in[5];
    const float* proj_b = (const float*)d_in[6];
    const int* rel = (const int*)d_in[7];
    float* out = (float*)d_out;

    cudaFuncSetAttribute(attn_kernel,
                         cudaFuncAttributeMaxDynamicSharedMemorySize,
                         SMEM_ATTN);

    rpb_kernel<<<(Hh * Nn * Nn + 255) / 256, 256>>>(rpb_table, rel);
    gemm3x<0><<<dim3(3 * Cc / BN, Mtot / BM), 256>>>(x, qkv_w, q_bias, v_bias,
                                                     nullptr);
    attn_kernel<<<dim3(4, Bb * Hh), 256, SMEM_ATTN>>>();
    gemm3x<1><<<dim3(Cc / BN, Mtot / BM), 256>>>(nullptr, proj_w, proj_b,
                                                 nullptr, out);
}

// round 4
// speedup vs baseline: 1.5678x; 1.5678x over previous
#include <cuda_runtime.h>
#include <cuda_bf16.h>
#include <cstdint>

#define DEV_INLINE __device__ __forceinline__

constexpr int Bb  = 256;
constexpr int Nn  = 196;
constexpr int Cc  = 768;
constexpr int Hh  = 12;
constexpr int HD  = 64;
constexpr int Mtot = Bb * Nn;          // 50176

// ---------------- scratch (device globals — allocation-free rule) ----------
__device__ __align__(16) float g_Q[(size_t)Bb * Hh * Nn * HD];
__device__ __align__(16) float g_K[(size_t)Bb * Hh * Nn * HD];
__device__ __align__(16) float g_V[(size_t)Bb * Hh * Nn * HD];
__device__ __align__(16) __nv_bfloat16 g_xh[(size_t)Mtot * Cc];
__device__ __align__(16) __nv_bfloat16 g_xl[(size_t)Mtot * Cc];
__device__ __align__(16) __nv_bfloat16 g_obh[(size_t)Mtot * Cc];
__device__ __align__(16) __nv_bfloat16 g_obl[(size_t)Mtot * Cc];
__device__ __align__(16) __nv_bfloat16 g_wqh[3 * Cc * Cc];
__device__ __align__(16) __nv_bfloat16 g_wql[3 * Cc * Cc];
__device__ __align__(16) __nv_bfloat16 g_wph[Cc * Cc];
__device__ __align__(16) __nv_bfloat16 g_wpl[Cc * Cc];
__device__ float g_rpb[Hh * Nn * Nn];

// ---------------- helpers ----------------
DEV_INLINE uint32_t smem_u32(const void* p) {
    uint32_t a;
    asm("{ .reg .u64 t; cvta.to.shared.u64 t, %1; cvt.u32.u64 %0, t; }"
        : "=r"(a) : "l"(p));
    return a;
}

DEV_INLINE uint32_t f2tf(float x) {
    uint32_t r;
    asm("cvt.rna.tf32.f32 %0, %1;" : "=r"(r) : "f"(x));
    return r;
}

DEV_INLINE void mma8(float* c, const uint32_t* a, const uint32_t* b) {
    asm volatile(
        "mma.sync.aligned.m16n8k8.row.col.f32.tf32.tf32.f32 "
        "{%0,%1,%2,%3}, {%4,%5,%6,%7}, {%8,%9}, {%0,%1,%2,%3};\n"
        : "+f"(c[0]), "+f"(c[1]), "+f"(c[2]), "+f"(c[3])
        : "r"(a[0]), "r"(a[1]), "r"(a[2]), "r"(a[3]), "r"(b[0]), "r"(b[1]));
}

DEV_INLINE void mma16bf(float* c, const uint32_t* a, const uint32_t* b) {
    asm volatile(
        "mma.sync.aligned.m16n8k16.row.col.f32.bf16.bf16.f32 "
        "{%0,%1,%2,%3}, {%4,%5,%6,%7}, {%8,%9}, {%0,%1,%2,%3};\n"
        : "+f"(c[0]), "+f"(c[1]), "+f"(c[2]), "+f"(c[3])
        : "r"(a[0]), "r"(a[1]), "r"(a[2]), "r"(a[3]), "r"(b[0]), "r"(b[1]));
}

DEV_INLINE void ldm4(uint32_t* r, uint32_t addr) {
    asm volatile(
        "ldmatrix.sync.aligned.m8n8.x4.shared.b16 {%0,%1,%2,%3}, [%4];"
        : "=r"(r[0]), "=r"(r[1]), "=r"(r[2]), "=r"(r[3]) : "r"(addr));
}

// ---------------- bf16 hi/lo split pre-pass ----------------
template <int WHICH>
__global__ void split_kernel(const float* __restrict__ src, int n4) {
    int i = blockIdx.x * 256 + threadIdx.x;
    if (i >= n4) return;
    __nv_bfloat162* hi;
    __nv_bfloat162* lo;
    if (WHICH == 0) { hi = (__nv_bfloat162*)g_xh; lo = (__nv_bfloat162*)g_xl; }
    else if (WHICH == 1) { hi = (__nv_bfloat162*)g_wqh; lo = (__nv_bfloat162*)g_wql; }
    else { hi = (__nv_bfloat162*)g_wph; lo = (__nv_bfloat162*)g_wpl; }
    float4 v = ((const float4*)src)[i];
    __nv_bfloat162 h0 = __floats2bfloat162_rn(v.x, v.y);
    __nv_bfloat162 h1 = __floats2bfloat162_rn(v.z, v.w);
    __nv_bfloat162 l0 = __floats2bfloat162_rn(v.x - __bfloat162float(h0.x),
                                              v.y - __bfloat162float(h0.y));
    __nv_bfloat162 l1 = __floats2bfloat162_rn(v.z - __bfloat162float(h1.x),
                                              v.w - __bfloat162float(h1.y));
    hi[i * 2] = h0; hi[i * 2 + 1] = h1;
    lo[i * 2] = l0; lo[i * 2 + 1] = l1;
}

// ---------------- rpb precompute ----------------
__global__ void rpb_kernel(const float* __restrict__ table,
                           const int* __restrict__ rel) {
    int idx = blockIdx.x * 256 + threadIdx.x;
    if (idx >= Hh * Nn * Nn) return;
    int h = idx / (Nn * Nn);
    int r = idx - h * Nn * Nn;
    g_rpb[idx] = table[(size_t)rel[r] * Hh + h];
}

// ------------- bf16-split GEMM: C[m,n] = sum_k A[m,k] W[n,k] ---------------
// Tiles: 128x128x32, 8 warps, warp = 32 rows x 64 cols. 3-stage cp.async.
constexpr int GK = 32;                 // bf16 per k-chunk
constexpr int LDB = 80;                // smem row stride in BYTES (64B data + 16B pad)
constexpr int ARR = 128 * LDB;         // 10240 B per array
constexpr int STG = 4 * ARR;           // Ah, Al, Bh, Bl
constexpr int NSTG = 3;
constexpr int SMEM_GEMM = NSTG * STG;  // 122880 B
constexpr int NCH = Cc / GK;           // 24

DEV_INLINE void load_stage(uint32_t sb, const __nv_bfloat16* Ah,
                           const __nv_bfloat16* Al, const __nv_bfloat16* Bh,
                           const __nv_bfloat16* Bl, int m0, int n0, int k0,
                           int tid) {
#pragma unroll
    for (int i = 0; i < 8; i++) {
        int idx = tid + i * 256;            // 0..2047
        int arr = idx >> 9;                  // 0..3 (const per i-pair)
        int rem = idx & 511;
        int r = rem >> 2, ch = rem & 3;
        const __nv_bfloat16* g = (arr == 0) ? Ah : (arr == 1) ? Al
                                : (arr == 2) ? Bh : Bl;
        int row0 = (arr < 2) ? m0 : n0;
        const char* src =
            (const char*)(g + (size_t)(row0 + r) * Cc + k0) + ch * 16;
        uint32_t dst = sb + arr * ARR + r * LDB + ch * 16;
        asm volatile("cp.async.cg.shared.global [%0], [%1], 16;\n"
                     :: "r"(dst), "l"(src));
    }
    asm volatile("cp.async.commit_group;\n" ::: "memory");
}

// MODE 0: A = x(split), W = qkv_w(split) -> g_Q/g_K/g_V (+bias, q-scale)
// MODE 1: A = Ob(split), W = proj_w(split) -> out (+proj bias)
template <int MODE>
__global__ void __launch_bounds__(256) gemm_bf(const float* __restrict__ b0,
                                               const float* __restrict__ b1,
                                               float* __restrict__ out) {
    extern __shared__ char dsm[];

    const __nv_bfloat16 *Ahg, *Alg, *Bhg, *Blg;
    if (MODE == 0) { Ahg = g_xh; Alg = g_xl; Bhg = g_wqh; Blg = g_wql; }
    else           { Ahg = g_obh; Alg = g_obl; Bhg = g_wph; Blg = g_wpl; }

    int tid = threadIdx.x, wid = tid >> 5, lane = tid & 31;
    int g = lane >> 2, t = lane & 3;
    int n0 = blockIdx.x * 128, m0 = blockIdx.y * 128;
    int wr = (wid & 3) * 32;       // warp row base (0..96)
    int wc = (wid >> 2) * 64;      // warp col base (0 or 64)

    uint32_t sbase = smem_u32(dsm);

    float acc[2][8][4];
#pragma unroll
    for (int i = 0; i < 2; i++)
#pragma unroll
        for (int j = 0; j < 8; j++)
#pragma unroll
            for (int e = 0; e < 4; e++) acc[i][j][e] = 0.f;

    // ldmatrix per-lane address components
    int lrow = (lane & 7) + ((lane >> 3) & 1) * 8;   // row within 16-tile
    int lk8 = (lane >> 4) * 8;                        // k-quad (0 or 8)

    // prologue: stages 0,1
    load_stage(sbase, Ahg, Alg, Bhg, Blg, m0, n0, 0, tid);
    load_stage(sbase + STG, Ahg, Alg, Bhg, Blg, m0, n0, GK, tid);

    for (int c = 0; c < NCH; c++) {
        if (c < NCH - 1)
            asm volatile("cp.async.wait_group 1;\n" ::: "memory");
        else
            asm volatile("cp.async.wait_group 0;\n" ::: "memory");
        __syncthreads();

        if (c + 2 < NCH) {
            int s = (c + 2) % NSTG;
            load_stage(sbase + s * STG, Ahg, Alg, Bhg, Blg, m0, n0,
                       (c + 2) * GK, tid);
        }

        uint32_t sb = sbase + (c % NSTG) * STG;
        uint32_t aA = sb + (wr + lrow) * LDB;
        uint32_t aAl = aA + ARR;
        uint32_t aB = sb + 2 * ARR + (wc + lrow) * LDB;
        uint32_t aBl = aB + ARR;

#pragma unroll
        for (int ks = 0; ks < 2; ks++) {       // two k16 steps per chunk
            uint32_t kb = (uint32_t)((ks * 16 + lk8) * 2);
            uint32_t ah[2][4], al[2][4], bh[4][4], bl[4][4];
#pragma unroll
            for (int i = 0; i < 2; i++) {
                ldm4(ah[i], aA + i * (16 * LDB) + kb);
                ldm4(al[i], aAl + i * (16 * LDB) + kb);
            }
#pragma unroll
            for (int jp = 0; jp < 4; jp++) {
                ldm4(bh[jp], aB + jp * (16 * LDB) + kb);
                ldm4(bl[jp], aBl + jp * (16 * LDB) + kb);
            }
#pragma unroll
            for (int i = 0; i < 2; i++)
#pragma unroll
                for (int j = 0; j < 8; j++) {
                    int jp = j >> 1, o = j & 1;
                    uint32_t bbh[2] = {bh[jp][o], bh[jp][2 + o]};
                    uint32_t bbl[2] = {bl[jp][o], bl[jp][2 + o]};
                    mma16bf(acc[i][j], ah[i], bbh);
                    mma16bf(acc[i][j], ah[i], bbl);
                    mma16bf(acc[i][j], al[i], bbh);
                }
        }
        __syncthreads();
    }

    // ---------------- epilogue ----------------
    if (MODE == 0) {
        int which = n0 / Cc;                       // 0=q 1=k 2=v
        int head = ((n0 % Cc) + wc) >> 6;          // constant per warp
        float* dst = (which == 0) ? g_Q : ((which == 1) ? g_K : g_V);
#pragma unroll
        for (int i = 0; i < 2; i++)
#pragma unroll
            for (int e = 0; e < 2; e++) {
                int m = m0 + wr + 16 * i + g + 8 * e;
                int bb = m / Nn, nn = m - bb * Nn;
                float* o = dst + (((size_t)bb * Hh + head) * Nn + nn) * HD;
#pragma unroll
                for (int j = 0; j < 8; j++) {
                    int d = 8 * j + 2 * t;
                    float v0 = acc[i][j][e * 2];
                    float v1 = acc[i][j][e * 2 + 1];
                    if (which == 0) {
                        v0 = (v0 + b0[head * HD + d]) * 0.125f;
                        v1 = (v1 + b0[head * HD + d + 1]) * 0.125f;
                    } else if (which == 2) {
                        v0 += b1[head * HD + d];
                        v1 += b1[head * HD + d + 1];
                    }
                    *(float2*)&o[d] = make_float2(v0, v1);
                }
            }
    } else {
#pragma unroll
        for (int i = 0; i < 2; i++)
#pragma unroll
            for (int e = 0; e < 2; e++) {
                int m = m0 + wr + 16 * i + g + 8 * e;
                float* o = out + (size_t)m * Cc + n0 + wc;
#pragma unroll
                for (int j = 0; j < 8; j++) {
                    int d = 8 * j + 2 * t;
                    float v0 = acc[i][j][e * 2] + b0[n0 + wc + d];
                    float v1 = acc[i][j][e * 2 + 1] + b0[n0 + wc + d + 1];
                    *(float2*)&o[d] = make_float2(v0, v1);
                }
            }
    }
}

// ---------------- fused window attention (tf32 mma.sync) -------------------
constexpr int QP = 68;
constexpr int SP = 260;
constexpr int SMEM_ATTN = (64 * QP * 2 + 64 * SP) * 4;

DEV_INLINE void load_kv_chunk(float* KVs, const float* src, size_t base,
                              int kc, int tid) {
#pragma unroll
    for (int it = 0; it < 4; ++it) {
        int idx = tid + it * 256;
        int row = idx >> 4, c4 = (idx & 15) * 4;
        int kn = kc * 64 + row;
        float4 v;
        if (kn < Nn)
            v = *(const float4*)(src + base + (size_t)kn * HD + c4);
        else
            v = make_float4(0.f, 0.f, 0.f, 0.f);
        float* p = (float*)&v;
#pragma unroll
        for (int q = 0; q < 4; q++) p[q] = __uint_as_float(f2tf(p[q]));
        *(float4*)&KVs[row * QP + c4] = v;
    }
}

__global__ void __launch_bounds__(256) attn_kernel() {
    extern __shared__ float sm[];
    float* Qs = sm;
    float* KVs = sm + 64 * QP;
    float* Ss = KVs + 64 * QP;

    int tid = threadIdx.x, wid = tid >> 5, lane = tid & 31;
    int g = lane >> 2, t = lane & 3;
    int mtile = blockIdx.x, bh = blockIdx.y;
    int b = bh / Hh, h = bh - b * Hh;
    int m0 = mtile * 64;
    size_t base = (size_t)bh * Nn * HD;
    int wr = (wid & 3) * 16, wc = (wid >> 2) * 32;

#pragma unroll
    for (int it = 0; it < 4; ++it) {
        int idx = tid + it * 256;
        int row = idx >> 4, c4 = (idx & 15) * 4;
        int n = m0 + row;
        float4 v;
        if (n < Nn)
            v = *(const float4*)(g_Q + base + (size_t)n * HD + c4);
        else
            v = make_float4(0.f, 0.f, 0.f, 0.f);
        float* p = (float*)&v;
#pragma unroll
        for (int q = 0; q < 4; q++) p[q] = __uint_as_float(f2tf(p[q]));
        *(float4*)&Qs[row * QP + c4] = v;
    }

    // S = Q K^T + rpb
    for (int kc = 0; kc < 4; ++kc) {
        __syncthreads();
        load_kv_chunk(KVs, g_K, base, kc, tid);
        __syncthreads();

        float acc[4][4];
#pragma unroll
        for (int j = 0; j < 4; j++)
#pragma unroll
            for (int e = 0; e < 4; e++) acc[j][e] = 0.f;

#pragma unroll
        for (int ks = 0; ks < 8; ++ks) {
            int kk = ks * 8;
            uint32_t a[4], bf[4][2];
            int r0 = wr + g;
            a[0] = __float_as_uint(Qs[r0 * QP + kk + t]);
            a[1] = __float_as_uint(Qs[(r0 + 8) * QP + kk + t]);
            a[2] = __float_as_uint(Qs[r0 * QP + kk + t + 4]);
            a[3] = __float_as_uint(Qs[(r0 + 8) * QP + kk + t + 4]);
#pragma unroll
            for (int j = 0; j < 4; j++) {
                int n = wc + 8 * j + g;
                bf[j][0] = __float_as_uint(KVs[n * QP + kk + t]);
                bf[j][1] = __float_as_uint(KVs[n * QP + kk + t + 4]);
            }
#pragma unroll
            for (int j = 0; j < 4; j++) mma8(acc[j], a, bf[j]);
        }

#pragma unroll
        for (int j = 0; j < 4; j++)
#pragma unroll
            for (int e2 = 0; e2 < 2; e2++) {
                int rl = wr + g + e2 * 8;
                int cl = wc + 8 * j + 2 * t;
                int qn = m0 + rl, kn = kc * 64 + cl;
                float r0v = 0.f, r1v = 0.f;
                if (qn < Nn) {
                    if (kn < Nn) r0v = g_rpb[((size_t)h * Nn + qn) * Nn + kn];
                    if (kn + 1 < Nn) r1v = g_rpb[((size_t)h * Nn + qn) * Nn + kn + 1];
                }
                Ss[rl * SP + kc * 64 + cl] = acc[j][e2 * 2] + r0v;
                Ss[rl * SP + kc * 64 + cl + 1] = acc[j][e2 * 2 + 1] + r1v;
            }
    }
    __syncthreads();

    // softmax
    for (int r8 = 0; r8 < 8; ++r8) {
        int r = wid * 8 + r8;
        float* row = Ss + r * SP;
        float mx = -1e30f;
#pragma unroll
        for (int c0 = 0; c0 < 7; c0++) {
            int c = lane + c0 * 32;
            if (c < Nn) mx = fmaxf(mx, row[c]);
        }
#pragma unroll
        for (int o = 16; o > 0; o >>= 1)
            mx = fmaxf(mx, __shfl_xor_sync(0xffffffffu, mx, o));
        float ev[7];
        float sum = 0.f;
#pragma unroll
        for (int c0 = 0; c0 < 7; c0++) {
            int c = lane + c0 * 32;
            float e = (c < Nn) ? __expf(row[c] - mx) : 0.f;
            ev[c0] = e;
            sum += e;
        }
#pragma unroll
        for (int o = 16; o > 0; o >>= 1)
            sum += __shfl_xor_sync(0xffffffffu, sum, o);
        float inv = 1.0f / sum;
#pragma unroll
        for (int c0 = 0; c0 < 7; c0++) {
            int c = lane + c0 * 32;
            if (c < Nn) row[c] = __uint_as_float(f2tf(ev[c0] * inv));
        }
#pragma unroll
        for (int c0 = 0; c0 < 2; c0++) {
            int c = Nn + lane + c0 * 32;
            if (c < 256) row[c] = 0.f;
        }
    }

    // O = P V
    float oac[4][4];
#pragma unroll
    for (int j = 0; j < 4; j++)
#pragma unroll
        for (int e = 0; e < 4; e++) oac[j][e] = 0.f;

    for (int kc = 0; kc < 4; ++kc) {
        __syncthreads();
        load_kv_chunk(KVs, g_V, base, kc, tid);
        __syncthreads();

#pragma unroll
        for (int ks = 0; ks < 8; ++ks) {
            int kk = kc * 64 + ks * 8;
            int kl = ks * 8;
            uint32_t a[4], bf[4][2];
            int r0 = wr + g;
            a[0] = __float_as_uint(Ss[r0 * SP + kk + t]);
            a[1] = __float_as_uint(Ss[(r0 + 8) * SP + kk + t]);
            a[2] = __float_as_uint(Ss[r0 * SP + kk + t + 4]);
            a[3] = __float_as_uint(Ss[(r0 + 8) * SP + kk + t + 4]);
#pragma unroll
            for (int j = 0; j < 4; j++) {
                int n = wc + 8 * j + g;
                bf[j][0] = __float_as_uint(KVs[(kl + t) * QP + n]);
                bf[j][1] = __float_as_uint(KVs[(kl + t + 4) * QP + n]);
            }
#pragma unroll
            for (int j = 0; j < 4; j++) mma8(oac[j], a, bf[j]);
        }
    }

    // epilogue: write bf16 hi/lo split of Ob for the proj GEMM
#pragma unroll
    for (int j = 0; j < 4; j++)
#pragma unroll
        for (int e2 = 0; e2 < 2; e2++) {
            int rl = wr + g + e2 * 8;
            int n = m0 + rl;
            if (n < Nn) {
                int d = wc + 8 * j + 2 * t;
                size_t off = ((size_t)(b * Nn + n)) * Cc + h * HD + d;
                float v0 = oac[j][e2 * 2], v1 = oac[j][e2 * 2 + 1];
                __nv_bfloat16 h0 = __float2bfloat16_rn(v0);
                __nv_bfloat16 h1 = __float2bfloat16_rn(v1);
                __nv_bfloat16 l0 =
                    __float2bfloat16_rn(v0 - __bfloat162float(h0));
                __nv_bfloat16 l1 =
                    __float2bfloat16_rn(v1 - __bfloat162float(h1));
                *(__nv_bfloat162*)&g_obh[off] = __halves2bfloat162(h0, h1);
                *(__nv_bfloat162*)&g_obl[off] = __halves2bfloat162(l0, l1);
            }
        }
}

// ---------------- launch ----------------
extern "C" void kernel_launch(void* const* d_in, const int* in_sizes, int n_in,
                              void* d_out, int out_size) {
    const float* x = (const float*)d_in[0];
    const float* qkv_w = (const float*)d_in[1];
    const float* q_bias = (const float*)d_in[2];
    const float* v_bias = (const float*)d_in[3];
    const float* rpb_table = (const float*)d_in[4];
    const float* proj_w = (const float*)d_in[5];
    const float* proj_b = (const float*)d_in[6];
    const int* rel = (const int*)d_in[7];
    float* out = (float*)d_out;

    cudaFuncSetAttribute(gemm_bf<0>, cudaFuncAttributeMaxDynamicSharedMemorySize,
                         SMEM_GEMM);
    cudaFuncSetAttribute(gemm_bf<1>, cudaFuncAttributeMaxDynamicSharedMemorySize,
                         SMEM_GEMM);
    cudaFuncSetAttribute(attn_kernel, cudaFuncAttributeMaxDynamicSharedMemorySize,
                         SMEM_ATTN);

    int nx4 = Mtot * Cc / 4;
    int nw4 = 3 * Cc * Cc / 4;
    int np4 = Cc * Cc / 4;
    split_kernel<0><<<(nx4 + 255) / 256, 256>>>(x, nx4);
    split_kernel<1><<<(nw4 + 255) / 256, 256>>>(qkv_w, nw4);
    split_kernel<2><<<(np4 + 255) / 256, 256>>>(proj_w, np4);
    rpb_kernel<<<(Hh * Nn * Nn + 255) / 256, 256>>>(rpb_table, rel);

    gemm_bf<0><<<dim3(3 * Cc / 128, Mtot / 128), 256, SMEM_GEMM>>>(
        q_bias, v_bias, nullptr);
    attn_kernel<<<dim3(4, Bb * Hh), 256, SMEM_ATTN>>>();
    gemm_bf<1><<<dim3(Cc / 128, Mtot / 128), 256, SMEM_GEMM>>>(proj_b, nullptr,
                                                               out);
}